// round 9
// baseline (speedup 1.0000x reference)
#include <cuda_runtime.h>
#include <cuda_fp16.h>
#include <cstdint>

#define NPTS 1048576
#define BSEG 2048
#define NCTA 148
#define NTHR 512

// smem byte offsets
//  W1H/W1L: [128 o][64 k] fp16, SW128 rows (16KB each)
//  W2H/W2L, W3H/W3L: 2 k-blocks of [128 o][64 k] (32KB each)
//  ACT: 2 buffers x (H 16KB + L 16KB); each H/L = 2 k-blocks of [64 pt][64 k]
#define O_W1H 0
#define O_W1L 16384
#define O_W2H 32768
#define O_W2L 65536
#define O_W3H 98304
#define O_W3L 131072
#define O_ACT 163840
#define O_SEGP 229376
#define O_POOL 229888
#define O_B2   230400
#define O_B3   230912
#define SMEM_BYTES 231424

#define SWZ(x) ((uint32_t)(x) ^ ((((uint32_t)(x)) >> 3) & 0x70))

__device__ __forceinline__ uint32_t smem_u32(const void* p) {
    uint32_t a;
    asm("{ .reg .u64 t; cvta.to.shared.u64 t, %1; cvt.u32.u64 %0, t; }" : "=r"(a) : "l"(p));
    return a;
}
__device__ __forceinline__ void ldsm_x4(uint32_t addr, uint32_t r[4]) {
    asm volatile("ldmatrix.sync.aligned.m8n8.x4.shared.b16 {%0,%1,%2,%3}, [%4];"
        : "=r"(r[0]), "=r"(r[1]), "=r"(r[2]), "=r"(r[3]) : "r"(addr));
}
__device__ __forceinline__ void mma16816(float c[4], const uint32_t a[4], const uint32_t b0, const uint32_t b1) {
    asm volatile("mma.sync.aligned.m16n8k16.row.col.f32.f16.f16.f32 "
        "{%0,%1,%2,%3},{%4,%5,%6,%7},{%8,%9},{%0,%1,%2,%3};"
        : "+f"(c[0]), "+f"(c[1]), "+f"(c[2]), "+f"(c[3])
        : "r"(a[0]), "r"(a[1]), "r"(a[2]), "r"(a[3]), "r"(b0), "r"(b1));
}
#define GBAR(g) asm volatile("bar.sync %0, 128;" :: "r"((g) + 1) : "memory")

// split v into fp16 hi + fp16 lo(residual); 2-byte stores
__device__ __forceinline__ void split_store2(char* bh, char* bl, uint32_t off, float v) {
    __half h = __float2half_rn(v);
    float r = v - __half2float(h);
    *(unsigned short*)(bh + off) = __half_as_ushort(h);
    *(unsigned short*)(bl + off) = __half_as_ushort(__float2half_rn(r));
}
// pack (v0,v1) -> hi word + lo word
__device__ __forceinline__ void split_pack2(float v0, float v1, uint32_t& hw, uint32_t& lw) {
    __half h0 = __float2half_rn(v0), h1 = __float2half_rn(v1);
    float r0 = v0 - __half2float(h0), r1 = v1 - __half2float(h1);
    hw = (uint32_t)__half_as_ushort(h0) | ((uint32_t)__half_as_ushort(h1) << 16);
    lw = (uint32_t)__half_as_ushort(__float2half_rn(r0))
       | ((uint32_t)__half_as_ushort(__float2half_rn(r1)) << 16);
}

// one layer: acc[4 nt][4] += split-fp16 A[16 x K] * W[K x 32 (quarter q)]
template<int KSTEPS>
__device__ __forceinline__ void run_layer(uint32_t aH, uint32_t aL,
                                          uint32_t wH, uint32_t wL,
                                          int grp, int q, int lane, float acc[4][4])
{
    const int arow  = grp * 16 + (lane & 15);
    const int acol  = (lane >> 4) * 8;
    const int wrow  = q * 32 + ((lane >> 4) << 3) + (lane & 7);
    const int wcsel = ((lane >> 3) & 1) << 3;
#pragma unroll
    for (int s = 0; s < KSTEPS; s++) {
        const int kb = s >> 2, kk = (s & 3) * 16;
        uint32_t ah[4], al[4], wh[2][4], wl[2][4];
        uint32_t aoff = SWZ(arow * 128 + (kk + acol) * 2);
        ldsm_x4(aH + kb * 8192 + aoff, ah);
        ldsm_x4(aL + kb * 8192 + aoff, al);
#pragma unroll
        for (int p2 = 0; p2 < 2; p2++) {
            uint32_t woff = SWZ((wrow + p2 * 16) * 128 + (kk + wcsel) * 2);
            ldsm_x4(wH + kb * 16384 + woff, wh[p2]);
            ldsm_x4(wL + kb * 16384 + woff, wl[p2]);
        }
#pragma unroll
        for (int p2 = 0; p2 < 2; p2++)
#pragma unroll
            for (int i = 0; i < 2; i++) {
                float* c = acc[p2 * 2 + i];
                mma16816(c, ah, wh[p2][2 * i], wh[p2][2 * i + 1]);
                mma16816(c, ah, wl[p2][2 * i], wl[p2][2 * i + 1]);
                mma16816(c, al, wh[p2][2 * i], wh[p2][2 * i + 1]);
            }
    }
}

// epilogue: bias + relu -> split fp16 -> swizzled act buffer (16 rows)
__device__ __forceinline__ void epi_store(char* sm_, uint32_t outOff,
                                          const float* bias, float acc[4][4],
                                          int grp, int q, int lane)
{
    const int row = grp * 16 + (lane >> 2);
    const int c0  = 2 * (lane & 3);
#pragma unroll
    for (int nt = 0; nt < 4; nt++) {
        int col = q * 32 + nt * 8 + c0;
        float2 bb = *(const float2*)(bias + col);
        float v0 = fmaxf(acc[nt][0] + bb.x, 0.f);
        float v1 = fmaxf(acc[nt][1] + bb.y, 0.f);
        float v2 = fmaxf(acc[nt][2] + bb.x, 0.f);
        float v3 = fmaxf(acc[nt][3] + bb.y, 0.f);
        uint32_t base = (uint32_t)(col >> 6) * 8192;
        int kk = col & 63;
        uint32_t off0 = base + SWZ(row * 128 + kk * 2);
        uint32_t off1 = base + SWZ((row + 8) * 128 + kk * 2);
        uint32_t hw, lw;
        split_pack2(v0, v1, hw, lw);
        *(uint32_t*)(sm_ + outOff + off0) = hw;
        *(uint32_t*)(sm_ + outOff + 16384 + off0) = lw;
        split_pack2(v2, v3, hw, lw);
        *(uint32_t*)(sm_ + outOff + off1) = hw;
        *(uint32_t*)(sm_ + outOff + 16384 + off1) = lw;
    }
}

// stage 16 rows of features (this group's slice) into buffer cols 0..63
// 128 threads: row = grp*16 + (t128>>3), cols (t128&7)*8 .. +7 (2 float4s)
__device__ __forceinline__ void stage_feats(char* sm_, uint32_t bufOff, int grp, int t128,
                                            const float4 f[2])
{
    int row = grp * 16 + (t128 >> 3);
    int k0  = (t128 & 7) * 8;
#pragma unroll
    for (int i = 0; i < 2; i++) {
        int k = k0 + 4 * i;
        uint32_t o0 = SWZ(row * 128 + k * 2);
        uint32_t o1 = SWZ(row * 128 + (k + 2) * 2);
        uint32_t hw, lw;
        split_pack2(f[i].x, f[i].y, hw, lw);
        *(uint32_t*)(sm_ + bufOff + o0) = hw;
        *(uint32_t*)(sm_ + bufOff + 16384 + o0) = lw;
        split_pack2(f[i].z, f[i].w, hw, lw);
        *(uint32_t*)(sm_ + bufOff + o1) = hw;
        *(uint32_t*)(sm_ + bufOff + 16384 + o1) = lw;
    }
}

__global__ void __launch_bounds__(NTHR, 1)
enc_kernel(const float* __restrict__ points, const float* __restrict__ features,
           const int* __restrict__ batch_words,
           const float* __restrict__ w_ne, const float* __restrict__ b_ne,
           const float* __restrict__ w1, const float* __restrict__ b1,
           const float* __restrict__ w2, const float* __restrict__ b2,
           const float* __restrict__ w3, const float* __restrict__ b3,
           const float* __restrict__ wg1, const float* __restrict__ bg1,
           const float* __restrict__ wg2, const float* __restrict__ bg2,
           const float* __restrict__ wg3, const float* __restrict__ bg3,
           float* __restrict__ out)
{
    extern __shared__ char sm[];
    const int tid = threadIdx.x, lane = tid & 31, wid = tid >> 5;
    const int grp = wid >> 2;                 // 4 groups of 4 warps
    const int q   = wid & 3;                  // output quarter (32 cols)
    const int t128 = tid & 127;
    const uint32_t smb = smem_u32(sm);

    float* segp   = (float*)(sm + O_SEGP);
    int*   pooled = (int*)(sm + O_POOL);
    float* b2s    = (float*)(sm + O_B2);
    float* b3s    = (float*)(sm + O_B3);
    float* actf   = (float*)(sm + O_ACT);     // pass-1 / head scratch alias

    // ---- stage weights as split-fp16, transposed [o][k], SW128 k-blocks ----
    for (int idx = tid; idx < 8192; idx += NTHR) {         // W1 rows 32..95
        int k = idx >> 7, o = idx & 127;
        split_store2(sm + O_W1H, sm + O_W1L, SWZ(o * 128 + k * 2), w1[(32 + k) * 128 + o]);
    }
    for (int idx = tid; idx < 16384; idx += NTHR) {
        int k = idx >> 7, o = idx & 127;
        uint32_t off = (uint32_t)(k >> 6) * 16384 + SWZ(o * 128 + (k & 63) * 2);
        split_store2(sm + O_W2H, sm + O_W2L, off, w2[k * 128 + o]);
        split_store2(sm + O_W3H, sm + O_W3L, off, w3[k * 128 + o]);
    }
    if (tid < 128) { b2s[tid] = b2[tid]; b3s[tid] = b3[tid]; }
    __syncthreads();

    const int stride = (batch_words[NPTS - 1] == 0) ? 2 : 1;   // int64 vs int32

    const int s0 = (blockIdx.x * BSEG) / NCTA;
    const int s1 = ((blockIdx.x + 1) * BSEG) / NCTA;

    for (int b = s0; b < s1; b++) {
        int lo, hi;
        {
            int l = 0, h = NPTS;
            while (l < h) { int m = (l + h) >> 1; if (batch_words[m * stride] < b) l = m + 1; else h = m; }
            lo = l; h = NPTS;
            while (l < h) { int m = (l + h) >> 1; if (batch_words[m * stride] < b + 1) l = m + 1; else h = m; }
            hi = l;
        }

        // ---- pass 1: encoder + segmax -> seg_part ----
        if (tid < 128) pooled[tid] = 0;
        if (tid < 96)  actf[tid] = w_ne[tid];
        if (tid < 32)  actf[96 + tid] = b_ne[tid];
        __syncthreads();
        {
            float em[32];
#pragma unroll
            for (int j = 0; j < 32; j++) em[j] = 0.f;
            const float* wne = actf; const float* bne = actf + 96;
            for (int n = lo + tid; n < hi; n += NTHR) {
                float x = points[3 * n], y = points[3 * n + 1], z = points[3 * n + 2];
#pragma unroll
                for (int j = 0; j < 32; j++)
                    em[j] = fmaxf(em[j], bne[j] + x * wne[j] + y * wne[32 + j] + z * wne[64 + j]);
            }
#pragma unroll
            for (int j = 0; j < 32; j++) {
#pragma unroll
                for (int o = 16; o > 0; o >>= 1)
                    em[j] = fmaxf(em[j], __shfl_xor_sync(0xFFFFFFFFu, em[j], o));
            }
            if (lane == 0) {
#pragma unroll
                for (int j = 0; j < 32; j++) actf[128 + wid * 32 + j] = em[j];
            }
            __syncthreads();
            if (tid < 32) {
                float m = actf[128 + tid];
#pragma unroll
                for (int p = 1; p < 16; p++) m = fmaxf(m, actf[128 + p * 32 + tid]);
                actf[768 + tid] = m;
            }
            __syncthreads();
            if (tid < 128) {
                float s = b1[tid];
#pragma unroll
                for (int k = 0; k < 32; k++) s += actf[768 + k] * w1[k * 128 + tid];
                segp[tid] = s;
            }
            __syncthreads();
        }

        // ---- pass 2: group-slices of 16 pts through the MLP on tensor cores ----
        float rm[8];
#pragma unroll
        for (int j = 0; j < 8; j++) rm[j] = 0.f;

        uint32_t offF = O_ACT, offX = O_ACT + 32768;   // F: features/L2out; X: L1out/L2in

        int n0 = lo + grp * 16;
        if (n0 < hi) {
            // stage slice 0 features
            float4 f[2];
            {
                int n = n0 + (t128 >> 3), k0 = (t128 & 7) * 8;
#pragma unroll
                for (int i = 0; i < 2; i++)
                    f[i] = (n < hi) ? *(const float4*)(features + (size_t)n * 64 + k0 + 4 * i)
                                    : make_float4(0.f, 0.f, 0.f, 0.f);
            }
            stage_feats(sm, offF, grp, t128, f);
            GBAR(grp);

            for (; n0 < hi; n0 += 64) {
                // prefetch next slice's features (overlaps with L1/L2 compute)
                float4 fn[2];
                {
                    int nn = n0 + 64 + (t128 >> 3), k0 = (t128 & 7) * 8;
#pragma unroll
                    for (int i = 0; i < 2; i++)
                        fn[i] = (nn < hi) ? *(const float4*)(features + (size_t)nn * 64 + k0 + 4 * i)
                                          : make_float4(0.f, 0.f, 0.f, 0.f);
                }

                float acc[4][4];
                // layer 1: K=64, F -> X, bias = seg_part
#pragma unroll
                for (int nt = 0; nt < 4; nt++)
                    acc[nt][0] = acc[nt][1] = acc[nt][2] = acc[nt][3] = 0.f;
                run_layer<4>(smb + offF, smb + offF + 16384, smb + O_W1H, smb + O_W1L,
                             grp, q, lane, acc);
                epi_store(sm, offX, segp, acc, grp, q, lane);
                GBAR(grp);

                // layer 2: K=128, X -> F, bias = b2
#pragma unroll
                for (int nt = 0; nt < 4; nt++)
                    acc[nt][0] = acc[nt][1] = acc[nt][2] = acc[nt][3] = 0.f;
                run_layer<8>(smb + offX, smb + offX + 16384, smb + O_W2H, smb + O_W2L,
                             grp, q, lane, acc);
                epi_store(sm, offF, b2s, acc, grp, q, lane);
                GBAR(grp);

                // stage NEXT slice's features into X (free after L2), overlapped with L3
                stage_feats(sm, offX, grp, t128, fn);

                // layer 3: K=128, reads F, bias = b3 -> masked running max
#pragma unroll
                for (int nt = 0; nt < 4; nt++)
                    acc[nt][0] = acc[nt][1] = acc[nt][2] = acc[nt][3] = 0.f;
                run_layer<8>(smb + offF, smb + offF + 16384, smb + O_W3H, smb + O_W3L,
                             grp, q, lane, acc);
                {
                    const int r0 = lane >> 2;
                    const int c0 = 2 * (lane & 3);
                    bool v0 = (n0 + r0) < hi;
                    bool v1 = (n0 + r0 + 8) < hi;
#pragma unroll
                    for (int nt = 0; nt < 4; nt++) {
                        int col = q * 32 + nt * 8 + c0;
                        float2 bb = *(const float2*)(b3s + col);
                        if (v0) {
                            rm[2 * nt]     = fmaxf(rm[2 * nt],     acc[nt][0] + bb.x);
                            rm[2 * nt + 1] = fmaxf(rm[2 * nt + 1], acc[nt][1] + bb.y);
                        }
                        if (v1) {
                            rm[2 * nt]     = fmaxf(rm[2 * nt],     acc[nt][2] + bb.x);
                            rm[2 * nt + 1] = fmaxf(rm[2 * nt + 1], acc[nt][3] + bb.y);
                        }
                    }
                }
                GBAR(grp);   // next features staged + F reads done
                uint32_t t = offF; offF = offX; offX = t;
            }
        }

        // reduce rm across lanes sharing the same columns (quad-stride groups)
#pragma unroll
        for (int j = 0; j < 8; j++) {
#pragma unroll
            for (int o = 4; o < 32; o <<= 1)
                rm[j] = fmaxf(rm[j], __shfl_xor_sync(0xFFFFFFFFu, rm[j], o));
        }
        if (lane < 4) {
#pragma unroll
            for (int nt = 0; nt < 4; nt++) {
                atomicMax(&pooled[q * 32 + nt * 8 + 2 * lane],     __float_as_int(rm[2 * nt]));
                atomicMax(&pooled[q * 32 + nt * 8 + 2 * lane + 1], __float_as_int(rm[2 * nt + 1]));
            }
        }
        __syncthreads();

        // ---- pass 3: head MLP 128 -> 128 -> 64 -> 32 ----
        if (tid < 128) {
            float s = bg1[tid];
#pragma unroll 8
            for (int k = 0; k < 128; k++) s += __int_as_float(pooled[k]) * wg1[k * 128 + tid];
            actf[tid] = fmaxf(s, 0.f);
        }
        __syncthreads();
        if (tid < 64) {
            float s = bg2[tid];
#pragma unroll 8
            for (int k = 0; k < 128; k++) s += actf[k] * wg2[k * 64 + tid];
            actf[128 + tid] = fmaxf(s, 0.f);
        }
        __syncthreads();
        if (tid < 32) {
            float s = bg3[tid];
#pragma unroll 8
            for (int k = 0; k < 64; k++) s += actf[128 + k] * wg3[k * 32 + tid];
            out[b * 32 + tid] = fmaxf(s, 0.f);
        }
        __syncthreads();
    }
}

extern "C" void kernel_launch(void* const* d_in, const int* in_sizes, int n_in,
                              void* d_out, int out_size)
{
    const float* points   = (const float*)d_in[0];
    const float* features = (const float*)d_in[1];
    const int*   batchw   = (const int*)  d_in[2];
    const float* w_ne = (const float*)d_in[3];
    const float* b_ne = (const float*)d_in[4];
    const float* w1   = (const float*)d_in[5];
    const float* b1   = (const float*)d_in[6];
    const float* w2   = (const float*)d_in[7];
    const float* b2   = (const float*)d_in[8];
    const float* w3   = (const float*)d_in[9];
    const float* b3   = (const float*)d_in[10];
    const float* wg1  = (const float*)d_in[11];
    const float* bg1  = (const float*)d_in[12];
    const float* wg2  = (const float*)d_in[13];
    const float* bg2  = (const float*)d_in[14];
    const float* wg3  = (const float*)d_in[15];
    const float* bg3  = (const float*)d_in[16];
    float* out = (float*)d_out;

    cudaFuncSetAttribute(enc_kernel, cudaFuncAttributeMaxDynamicSharedMemorySize, SMEM_BYTES);
    enc_kernel<<<NCTA, NTHR, SMEM_BYTES>>>(
        points, features, batchw,
        w_ne, b_ne, w1, b1, w2, b2, w3, b3,
        wg1, bg1, wg2, bg2, wg3, bg3, out);
}

// round 10
// speedup vs baseline: 1.1853x; 1.1853x over previous
#include <cuda_runtime.h>
#include <cuda_fp16.h>
#include <cstdint>

#define NPTS 1048576
#define BSEG 2048
#define NCTA 148
#define NTHR 512

// smem byte offsets
//  W1: [128 o][64 k] fp16 (hi only), SW128 (16KB)
//  W2, W3: 2 k-blocks of [128 o][64 k] (32KB each)
//  ACTF/ACTX: 2 buffers, each H(32KB: 128 rows x 128 cols, 2 k-blocks) + L(32KB)
#define O_W1   0
#define O_W2   16384
#define O_W3   49152
#define O_ACTF 81920
#define O_ACTX 147456
#define O_SEGP 212992
#define O_POOL 213504
#define O_B2   214016
#define O_B3   214528
#define SMEM_BYTES 215040

#define SWZ(x) ((uint32_t)(x) ^ ((((uint32_t)(x)) >> 3) & 0x70))

__device__ __forceinline__ uint32_t smem_u32(const void* p) {
    uint32_t a;
    asm("{ .reg .u64 t; cvta.to.shared.u64 t, %1; cvt.u32.u64 %0, t; }" : "=r"(a) : "l"(p));
    return a;
}
__device__ __forceinline__ void ldsm_x4(uint32_t addr, uint32_t r[4]) {
    asm volatile("ldmatrix.sync.aligned.m8n8.x4.shared.b16 {%0,%1,%2,%3}, [%4];"
        : "=r"(r[0]), "=r"(r[1]), "=r"(r[2]), "=r"(r[3]) : "r"(addr));
}
__device__ __forceinline__ void mma16816(float c[4], const uint32_t a[4], const uint32_t b0, const uint32_t b1) {
    asm volatile("mma.sync.aligned.m16n8k16.row.col.f32.f16.f16.f32 "
        "{%0,%1,%2,%3},{%4,%5,%6,%7},{%8,%9},{%0,%1,%2,%3};"
        : "+f"(c[0]), "+f"(c[1]), "+f"(c[2]), "+f"(c[3])
        : "r"(a[0]), "r"(a[1]), "r"(a[2]), "r"(a[3]), "r"(b0), "r"(b1));
}
#define PBAR(p) asm volatile("bar.sync %0, 64;" :: "r"((p) + 1) : "memory")

// pack (v0,v1) -> fp16 hi word + fp16 lo(residual) word
__device__ __forceinline__ void split_pack2(float v0, float v1, uint32_t& hw, uint32_t& lw) {
    __half h0 = __float2half_rn(v0), h1 = __float2half_rn(v1);
    float r0 = v0 - __half2float(h0), r1 = v1 - __half2float(h1);
    hw = (uint32_t)__half_as_ushort(h0) | ((uint32_t)__half_as_ushort(h1) << 16);
    lw = (uint32_t)__half_as_ushort(__float2half_rn(r0))
       | ((uint32_t)__half_as_ushort(__float2half_rn(r1)) << 16);
}

// one layer: acc[8 nt][4] += (Ah+Al)[16 x K] * Wh[K x 64 (half nh)]
// act k-block stride = 16384 (128 rows); W k-block stride = 16384 (128 o-rows)
template<int KSTEPS>
__device__ __forceinline__ void run_layer(uint32_t aH, uint32_t aL, uint32_t wBase,
                                          int rowbase, int nh, int lane, float acc[8][4])
{
    const int arow  = rowbase + (lane & 15);
    const int acol  = (lane >> 4) * 8;
    const int wrow  = nh * 64 + ((lane >> 4) << 3) + (lane & 7);
    const int wcsel = ((lane >> 3) & 1) << 3;
#pragma unroll
    for (int s = 0; s < KSTEPS; s++) {
        const int kb = s >> 2, kk = (s & 3) * 16;
        uint32_t ah[4], al[4], wh[4][4];
        uint32_t aoff = (uint32_t)kb * 16384 + SWZ(arow * 128 + (kk + acol) * 2);
        ldsm_x4(aH + aoff, ah);
        ldsm_x4(aL + aoff, al);
#pragma unroll
        for (int p4 = 0; p4 < 4; p4++) {
            uint32_t woff = (uint32_t)kb * 16384 + SWZ((wrow + p4 * 16) * 128 + (kk + wcsel) * 2);
            ldsm_x4(wBase + woff, wh[p4]);
        }
#pragma unroll
        for (int p4 = 0; p4 < 4; p4++)
#pragma unroll
            for (int i = 0; i < 2; i++) {
                float* c = acc[p4 * 2 + i];
                mma16816(c, ah, wh[p4][2 * i], wh[p4][2 * i + 1]);
                mma16816(c, al, wh[p4][2 * i], wh[p4][2 * i + 1]);
            }
    }
}

// epilogue: bias + relu -> split fp16 -> swizzled act buffer (16 rows x 64 cols)
__device__ __forceinline__ void epi_store(char* sm_, uint32_t outOff,
                                          const float* bias, float acc[8][4],
                                          int rowbase, int nh, int lane)
{
    const int row = rowbase + (lane >> 2);
    const int c0  = 2 * (lane & 3);
    const uint32_t kbb = (uint32_t)nh * 16384;
#pragma unroll
    for (int nt = 0; nt < 8; nt++) {
        int col = nh * 64 + nt * 8 + c0;
        float2 bb = *(const float2*)(bias + col);
        float v0 = fmaxf(acc[nt][0] + bb.x, 0.f);
        float v1 = fmaxf(acc[nt][1] + bb.y, 0.f);
        float v2 = fmaxf(acc[nt][2] + bb.x, 0.f);
        float v3 = fmaxf(acc[nt][3] + bb.y, 0.f);
        int kk = col & 63;
        uint32_t off0 = kbb + SWZ(row * 128 + kk * 2);
        uint32_t off1 = kbb + SWZ((row + 8) * 128 + kk * 2);
        uint32_t hw, lw;
        split_pack2(v0, v1, hw, lw);
        *(uint32_t*)(sm_ + outOff + off0) = hw;
        *(uint32_t*)(sm_ + outOff + 32768 + off0) = lw;
        split_pack2(v2, v3, hw, lw);
        *(uint32_t*)(sm_ + outOff + off1) = hw;
        *(uint32_t*)(sm_ + outOff + 32768 + off1) = lw;
    }
}

// stage 16 rows of features (pair slice) into buffer cols 0..63 (k-block 0)
// 64 threads: row = rowbase + (t64>>2), k0 = (t64&3)*16, 4 float4s
__device__ __forceinline__ void stage_feats(char* sm_, uint32_t bufOff, int rowbase, int t64,
                                            const float4 f[4])
{
    int row = rowbase + (t64 >> 2);
    int k0  = (t64 & 3) * 16;
#pragma unroll
    for (int i = 0; i < 4; i++) {
        int k = k0 + 4 * i;
        uint32_t o0 = SWZ(row * 128 + k * 2);
        uint32_t o1 = SWZ(row * 128 + (k + 2) * 2);
        uint32_t hw, lw;
        split_pack2(f[i].x, f[i].y, hw, lw);
        *(uint32_t*)(sm_ + bufOff + o0) = hw;
        *(uint32_t*)(sm_ + bufOff + 32768 + o0) = lw;
        split_pack2(f[i].z, f[i].w, hw, lw);
        *(uint32_t*)(sm_ + bufOff + o1) = hw;
        *(uint32_t*)(sm_ + bufOff + 32768 + o1) = lw;
    }
}

__global__ void __launch_bounds__(NTHR, 1)
enc_kernel(const float* __restrict__ points, const float* __restrict__ features,
           const int* __restrict__ batch_words,
           const float* __restrict__ w_ne, const float* __restrict__ b_ne,
           const float* __restrict__ w1, const float* __restrict__ b1,
           const float* __restrict__ w2, const float* __restrict__ b2,
           const float* __restrict__ w3, const float* __restrict__ b3,
           const float* __restrict__ wg1, const float* __restrict__ bg1,
           const float* __restrict__ wg2, const float* __restrict__ bg2,
           const float* __restrict__ wg3, const float* __restrict__ bg3,
           float* __restrict__ out)
{
    extern __shared__ char sm[];
    const int tid = threadIdx.x, lane = tid & 31, wid = tid >> 5;
    const int pair = wid >> 1;                // 8 independent pairs
    const int nh   = wid & 1;                 // output half (64 cols)
    const int t64  = tid & 63;
    const int rowbase = pair * 16;
    const uint32_t smb = smem_u32(sm);

    float* segp   = (float*)(sm + O_SEGP);
    int*   pooled = (int*)(sm + O_POOL);
    float* b2s    = (float*)(sm + O_B2);
    float* b3s    = (float*)(sm + O_B3);
    float* actf   = (float*)(sm + O_ACTF);    // pass-1 / head scratch alias

    // ---- stage weights fp16-hi, transposed [o][k], SW128 k-blocks ----
    for (int idx = tid; idx < 8192; idx += NTHR) {         // W1 rows 32..95
        int k = idx >> 7, o = idx & 127;
        *(unsigned short*)(sm + O_W1 + SWZ(o * 128 + k * 2)) =
            __half_as_ushort(__float2half_rn(w1[(32 + k) * 128 + o]));
    }
    for (int idx = tid; idx < 16384; idx += NTHR) {
        int k = idx >> 7, o = idx & 127;
        uint32_t off = (uint32_t)(k >> 6) * 16384 + SWZ(o * 128 + (k & 63) * 2);
        *(unsigned short*)(sm + O_W2 + off) = __half_as_ushort(__float2half_rn(w2[k * 128 + o]));
        *(unsigned short*)(sm + O_W3 + off) = __half_as_ushort(__float2half_rn(w3[k * 128 + o]));
    }
    if (tid < 128) { b2s[tid] = b2[tid]; b3s[tid] = b3[tid]; }
    __syncthreads();

    const int stride = (batch_words[NPTS - 1] == 0) ? 2 : 1;   // int64 vs int32

    const int s0 = (blockIdx.x * BSEG) / NCTA;
    const int s1 = ((blockIdx.x + 1) * BSEG) / NCTA;

    for (int b = s0; b < s1; b++) {
        int lo, hi;
        {
            int l = 0, h = NPTS;
            while (l < h) { int m = (l + h) >> 1; if (batch_words[m * stride] < b) l = m + 1; else h = m; }
            lo = l; h = NPTS;
            while (l < h) { int m = (l + h) >> 1; if (batch_words[m * stride] < b + 1) l = m + 1; else h = m; }
            hi = l;
        }

        // ---- pass 1: encoder + segmax -> seg_part ----
        if (tid < 128) pooled[tid] = 0;
        if (tid < 96)  actf[tid] = w_ne[tid];
        if (tid < 32)  actf[96 + tid] = b_ne[tid];
        __syncthreads();
        {
            float em[32];
#pragma unroll
            for (int j = 0; j < 32; j++) em[j] = 0.f;
            const float* wne = actf; const float* bne = actf + 96;
            for (int n = lo + tid; n < hi; n += NTHR) {
                float x = points[3 * n], y = points[3 * n + 1], z = points[3 * n + 2];
#pragma unroll
                for (int j = 0; j < 32; j++)
                    em[j] = fmaxf(em[j], bne[j] + x * wne[j] + y * wne[32 + j] + z * wne[64 + j]);
            }
#pragma unroll
            for (int j = 0; j < 32; j++) {
#pragma unroll
                for (int o = 16; o > 0; o >>= 1)
                    em[j] = fmaxf(em[j], __shfl_xor_sync(0xFFFFFFFFu, em[j], o));
            }
            if (lane == 0) {
#pragma unroll
                for (int j = 0; j < 32; j++) actf[128 + wid * 32 + j] = em[j];
            }
            __syncthreads();
            if (tid < 32) {
                float m = actf[128 + tid];
#pragma unroll
                for (int p = 1; p < 16; p++) m = fmaxf(m, actf[128 + p * 32 + tid]);
                actf[768 + tid] = m;
            }
            __syncthreads();
            if (tid < 128) {
                float s = b1[tid];
#pragma unroll
                for (int k = 0; k < 32; k++) s += actf[768 + k] * w1[k * 128 + tid];
                segp[tid] = s;
            }
            __syncthreads();
        }

        // ---- pass 2: 8 independent pair-slices of 16 pts, 128 pts per sweep ----
        float rm[8];
#pragma unroll
        for (int j = 0; j < 8; j++) rm[j] = 0.f;

        uint32_t offF = O_ACTF, offX = O_ACTX;

        int n0 = lo + rowbase;
        if (n0 < hi) {
            float4 f[4];
            {
                int n = n0 + (t64 >> 2), k0 = (t64 & 3) * 16;
#pragma unroll
                for (int i = 0; i < 4; i++)
                    f[i] = (n < hi) ? *(const float4*)(features + (size_t)n * 64 + k0 + 4 * i)
                                    : make_float4(0.f, 0.f, 0.f, 0.f);
            }
            stage_feats(sm, offF, rowbase, t64, f);
            PBAR(pair);

            for (; n0 < hi; n0 += 128) {
                // prefetch next sweep's features (overlaps L1/L2 compute)
                float4 fn[4];
                {
                    int nn = n0 + 128 + (t64 >> 2), k0 = (t64 & 3) * 16;
#pragma unroll
                    for (int i = 0; i < 4; i++)
                        fn[i] = (nn < hi) ? *(const float4*)(features + (size_t)nn * 64 + k0 + 4 * i)
                                          : make_float4(0.f, 0.f, 0.f, 0.f);
                }

                float acc[8][4];
                // layer 1: K=64, F -> X, bias = seg_part
#pragma unroll
                for (int nt = 0; nt < 8; nt++)
                    acc[nt][0] = acc[nt][1] = acc[nt][2] = acc[nt][3] = 0.f;
                run_layer<4>(smb + offF, smb + offF + 32768, smb + O_W1,
                             rowbase, nh, lane, acc);
                epi_store(sm, offX, segp, acc, rowbase, nh, lane);
                PBAR(pair);

                // layer 2: K=128, X -> F, bias = b2
#pragma unroll
                for (int nt = 0; nt < 8; nt++)
                    acc[nt][0] = acc[nt][1] = acc[nt][2] = acc[nt][3] = 0.f;
                run_layer<8>(smb + offX, smb + offX + 32768, smb + O_W2,
                             rowbase, nh, lane, acc);
                epi_store(sm, offF, b2s, acc, rowbase, nh, lane);
                PBAR(pair);

                // stage NEXT sweep's features into X (free after L2), overlapped with L3
                stage_feats(sm, offX, rowbase, t64, fn);

                // layer 3: K=128, reads F, bias = b3 -> masked running max
#pragma unroll
                for (int nt = 0; nt < 8; nt++)
                    acc[nt][0] = acc[nt][1] = acc[nt][2] = acc[nt][3] = 0.f;
                run_layer<8>(smb + offF, smb + offF + 32768, smb + O_W3,
                             rowbase, nh, lane, acc);
                {
                    const int r0 = lane >> 2;
                    const int c0 = 2 * (lane & 3);
                    bool v0 = (n0 + r0) < hi;
                    bool v1 = (n0 + r0 + 8) < hi;
#pragma unroll
                    for (int nt = 0; nt < 8; nt++) {
                        int col = nh * 64 + nt * 8 + c0;
                        float2 bb = *(const float2*)(b3s + col);
                        if (v0) {
                            rm[nt] = fmaxf(rm[nt], acc[nt][0] + bb.x);
                            // interleave: rm[nt] covers col, need col+1 too -> use pairs below
                        }
                    }
                    // handle both columns per nt with separate slots
#pragma unroll
                    for (int nt = 0; nt < 4; nt++) {
                        int col = nh * 64 + nt * 8 + c0;
                        (void)col;
                    }
                    // NOTE: full handling below replaces the partial loop above
                }
                // full masked max (8 slots: nt pairs of 2 cols -> rm[2i],rm[2i+1] for nt<4 insufficient)
                // Use rm[8] as col slots for nt 0..3 x 2 cols? We need 16 values; reduce now:
                {
                    const int r0 = lane >> 2;
                    const int c0 = 2 * (lane & 3);
                    bool v0 = (n0 + r0) < hi;
                    bool v1 = (n0 + r0 + 8) < hi;
#pragma unroll
                    for (int nt = 0; nt < 8; nt++) {
                        int col = nh * 64 + nt * 8 + c0;
                        float2 bb = *(const float2*)(b3s + col);
                        float m0 = -1.f, m1 = -1.f;
                        if (v0) { m0 = acc[nt][0] + bb.x; m1 = acc[nt][1] + bb.y; }
                        if (v1) { m0 = fmaxf(m0, acc[nt][2] + bb.x); m1 = fmaxf(m1, acc[nt][3] + bb.y); }
                        // fold the two columns into rm[nt] via lane-parity trick is fragile;
                        // instead reduce immediately across the 8 row-lanes and atomically max.
#pragma unroll
                        for (int o = 4; o < 32; o <<= 1) {
                            m0 = fmaxf(m0, __shfl_xor_sync(0xFFFFFFFFu, m0, o));
                            m1 = fmaxf(m1, __shfl_xor_sync(0xFFFFFFFFu, m1, o));
                        }
                        if (lane < 4) {
                            rm[nt] = fmaxf(rm[nt], fmaxf(m0, 0.f));
                            // m1 belongs to col+1; stash via second array slot trick:
                        }
                        if (lane < 4) {
                            // col+1 running max kept in smem atomics directly (cheap: 8 nt x 1 lane group)
                            atomicMax(&pooled[col + 1], __float_as_int(fmaxf(m1, 0.f)));
                        }
                    }
                }
                PBAR(pair);   // next features staged + F reads done
                uint32_t t = offF; offF = offX; offX = t;
            }
        }

        // flush rm (even columns) into pooled
        if (lane < 4) {
#pragma unroll
            for (int nt = 0; nt < 8; nt++) {
                int col = nh * 64 + nt * 8 + 2 * lane;
                atomicMax(&pooled[col], __float_as_int(rm[nt]));
            }
        }
        __syncthreads();

        // ---- pass 3: head MLP 128 -> 128 -> 64 -> 32 ----
        if (tid < 128) {
            float s = bg1[tid];
#pragma unroll 8
            for (int k = 0; k < 128; k++) s += __int_as_float(pooled[k]) * wg1[k * 128 + tid];
            actf[tid] = fmaxf(s, 0.f);
        }
        __syncthreads();
        if (tid < 64) {
            float s = bg2[tid];
#pragma unroll 8
            for (int k = 0; k < 128; k++) s += actf[k] * wg2[k * 64 + tid];
            actf[128 + tid] = fmaxf(s, 0.f);
        }
        __syncthreads();
        if (tid < 32) {
            float s = bg3[tid];
#pragma unroll 8
            for (int k = 0; k < 64; k++) s += actf[128 + k] * wg3[k * 32 + tid];
            out[b * 32 + tid] = fmaxf(s, 0.f);
        }
        __syncthreads();
    }
}

extern "C" void kernel_launch(void* const* d_in, const int* in_sizes, int n_in,
                              void* d_out, int out_size)
{
    const float* points   = (const float*)d_in[0];
    const float* features = (const float*)d_in[1];
    const int*   batchw   = (const int*)  d_in[2];
    const float* w_ne = (const float*)d_in[3];
    const float* b_ne = (const float*)d_in[4];
    const float* w1   = (const float*)d_in[5];
    const float* b1   = (const float*)d_in[6];
    const float* w2   = (const float*)d_in[7];
    const float* b2   = (const float*)d_in[8];
    const float* w3   = (const float*)d_in[9];
    const float* b3   = (const float*)d_in[10];
    const float* wg1  = (const float*)d_in[11];
    const float* bg1  = (const float*)d_in[12];
    const float* wg2  = (const float*)d_in[13];
    const float* bg2  = (const float*)d_in[14];
    const float* wg3  = (const float*)d_in[15];
    const float* bg3  = (const float*)d_in[16];
    float* out = (float*)d_out;

    cudaFuncSetAttribute(enc_kernel, cudaFuncAttributeMaxDynamicSharedMemorySize, SMEM_BYTES);
    enc_kernel<<<NCTA, NTHR, SMEM_BYTES>>>(
        points, features, batchw,
        w_ne, b_ne, w1, b1, w2, b2, w3, b3,
        wg1, bg1, wg2, bg2, wg3, bg3, out);
}

// round 11
// speedup vs baseline: 1.5613x; 1.3172x over previous
#include <cuda_runtime.h>
#include <cuda_fp16.h>
#include <cstdint>

#define NPTS 1048576
#define BSEG 2048
#define NCTA 148
#define NTHR 512

// smem byte offsets (all fp16 single precision; weights + acts)
//  W1: [128 o][64 k] SW128 (16KB)
//  W2, W3: 2 k-blocks of [128 o][64 k] (32KB each)
//  ACTF/ACTX: 2 act buffers, each 2 k-blocks of [128 rows][64 cols] fp16 (32KB each)
#define O_W1   0
#define O_W2   16384
#define O_W3   49152
#define O_ACTF 81920
#define O_ACTX 114688
#define O_SEGP 147456
#define O_POOL 147968
#define O_B2   148480
#define O_B3   148992
#define SMEM_BYTES 149504

#define SWZ(x) ((uint32_t)(x) ^ ((((uint32_t)(x)) >> 3) & 0x70))

__device__ __forceinline__ uint32_t smem_u32(const void* p) {
    uint32_t a;
    asm("{ .reg .u64 t; cvta.to.shared.u64 t, %1; cvt.u32.u64 %0, t; }" : "=r"(a) : "l"(p));
    return a;
}
__device__ __forceinline__ void ldsm_x4(uint32_t addr, uint32_t r[4]) {
    asm volatile("ldmatrix.sync.aligned.m8n8.x4.shared.b16 {%0,%1,%2,%3}, [%4];"
        : "=r"(r[0]), "=r"(r[1]), "=r"(r[2]), "=r"(r[3]) : "r"(addr));
}
__device__ __forceinline__ void mma16816(float c[4], const uint32_t a[4], const uint32_t b0, const uint32_t b1) {
    asm volatile("mma.sync.aligned.m16n8k16.row.col.f32.f16.f16.f32 "
        "{%0,%1,%2,%3},{%4,%5,%6,%7},{%8,%9},{%0,%1,%2,%3};"
        : "+f"(c[0]), "+f"(c[1]), "+f"(c[2]), "+f"(c[3])
        : "r"(a[0]), "r"(a[1]), "r"(a[2]), "r"(a[3]), "r"(b0), "r"(b1));
}
#define PBAR(p) asm volatile("bar.sync %0, 64;" :: "r"((p) + 1) : "memory")

// pack two floats -> one fp16x2 word (single F2FP instruction), lo = v0
__device__ __forceinline__ uint32_t packh2(float v0, float v1) {
    __half2 h = __floats2half2_rn(v0, v1);
    return *(uint32_t*)&h;
}

// one layer: acc[8 nt][4] += A[16 x K] * W[K x 64 (half nh)]  (pure fp16 operands)
// act k-block stride = 16384 (128 rows x 128B); W k-block stride = 16384
template<int KSTEPS>
__device__ __forceinline__ void run_layer(uint32_t aBase, uint32_t wBase,
                                          int rowbase, int nh, int lane, float acc[8][4])
{
    const int arow  = rowbase + (lane & 15);
    const int acol  = (lane >> 4) * 8;
    const int wrow  = nh * 64 + ((lane >> 4) << 3) + (lane & 7);
    const int wcsel = ((lane >> 3) & 1) << 3;
#pragma unroll
    for (int s = 0; s < KSTEPS; s++) {
        const int kb = s >> 2, kk = (s & 3) * 16;
        uint32_t ah[4], wh[4][4];
        ldsm_x4(aBase + (uint32_t)kb * 16384 + SWZ(arow * 128 + (kk + acol) * 2), ah);
#pragma unroll
        for (int p4 = 0; p4 < 4; p4++)
            ldsm_x4(wBase + (uint32_t)kb * 16384 + SWZ((wrow + p4 * 16) * 128 + (kk + wcsel) * 2), wh[p4]);
#pragma unroll
        for (int p4 = 0; p4 < 4; p4++)
#pragma unroll
            for (int i = 0; i < 2; i++)
                mma16816(acc[p4 * 2 + i], ah, wh[p4][2 * i], wh[p4][2 * i + 1]);
    }
}

// epilogue: bias + relu -> fp16 -> swizzled act buffer (16 rows x 64 cols of this half)
__device__ __forceinline__ void epi_store(char* sm_, uint32_t outOff,
                                          const float* bias, float acc[8][4],
                                          int rowbase, int nh, int lane)
{
    const int row = rowbase + (lane >> 2);
    const int c0  = 2 * (lane & 3);
    const uint32_t kbb = (uint32_t)nh * 16384;
#pragma unroll
    for (int nt = 0; nt < 8; nt++) {
        int col = nh * 64 + nt * 8 + c0;
        float2 bb = *(const float2*)(bias + col);
        int kk = col & 63;
        uint32_t off0 = kbb + SWZ(row * 128 + kk * 2);
        uint32_t off1 = kbb + SWZ((row + 8) * 128 + kk * 2);
        *(uint32_t*)(sm_ + outOff + off0) =
            packh2(fmaxf(acc[nt][0] + bb.x, 0.f), fmaxf(acc[nt][1] + bb.y, 0.f));
        *(uint32_t*)(sm_ + outOff + off1) =
            packh2(fmaxf(acc[nt][2] + bb.x, 0.f), fmaxf(acc[nt][3] + bb.y, 0.f));
    }
}

// stage 16 rows of features (pair slice) into buffer k-block 0
// 64 threads: row = rowbase + (t64>>2), k0 = (t64&3)*16, 4 float4s per thread
__device__ __forceinline__ void stage_feats(char* sm_, uint32_t bufOff, int rowbase, int t64,
                                            const float4 f[4])
{
    int row = rowbase + (t64 >> 2);
    int k0  = (t64 & 3) * 16;
#pragma unroll
    for (int i = 0; i < 4; i++) {
        int k = k0 + 4 * i;
        *(uint32_t*)(sm_ + bufOff + SWZ(row * 128 + k * 2))       = packh2(f[i].x, f[i].y);
        *(uint32_t*)(sm_ + bufOff + SWZ(row * 128 + (k + 2) * 2)) = packh2(f[i].z, f[i].w);
    }
}

__global__ void __launch_bounds__(NTHR, 1)
enc_kernel(const float* __restrict__ points, const float* __restrict__ features,
           const int* __restrict__ batch_words,
           const float* __restrict__ w_ne, const float* __restrict__ b_ne,
           const float* __restrict__ w1, const float* __restrict__ b1,
           const float* __restrict__ w2, const float* __restrict__ b2,
           const float* __restrict__ w3, const float* __restrict__ b3,
           const float* __restrict__ wg1, const float* __restrict__ bg1,
           const float* __restrict__ wg2, const float* __restrict__ bg2,
           const float* __restrict__ wg3, const float* __restrict__ bg3,
           float* __restrict__ out)
{
    extern __shared__ char sm[];
    const int tid = threadIdx.x, lane = tid & 31, wid = tid >> 5;
    const int pair = wid >> 1;                // 8 independent pairs
    const int nh   = wid & 1;                 // output half (64 cols)
    const int t64  = tid & 63;
    const int rowbase = pair * 16;
    const uint32_t smb = smem_u32(sm);

    float* segp   = (float*)(sm + O_SEGP);
    int*   pooled = (int*)(sm + O_POOL);
    float* b2s    = (float*)(sm + O_B2);
    float* b3s    = (float*)(sm + O_B3);
    float* actf   = (float*)(sm + O_ACTF);    // pass-1 / head scratch alias

    // ---- stage weights fp16, transposed [o][k], SW128 k-blocks ----
    for (int idx = tid; idx < 8192; idx += NTHR) {         // W1 rows 32..95
        int k = idx >> 7, o = idx & 127;
        *(unsigned short*)(sm + O_W1 + SWZ(o * 128 + k * 2)) =
            __half_as_ushort(__float2half_rn(w1[(32 + k) * 128 + o]));
    }
    for (int idx = tid; idx < 16384; idx += NTHR) {
        int k = idx >> 7, o = idx & 127;
        uint32_t off = (uint32_t)(k >> 6) * 16384 + SWZ(o * 128 + (k & 63) * 2);
        *(unsigned short*)(sm + O_W2 + off) = __half_as_ushort(__float2half_rn(w2[k * 128 + o]));
        *(unsigned short*)(sm + O_W3 + off) = __half_as_ushort(__float2half_rn(w3[k * 128 + o]));
    }
    if (tid < 128) { b2s[tid] = b2[tid]; b3s[tid] = b3[tid]; }
    __syncthreads();

    const int stride = (batch_words[NPTS - 1] == 0) ? 2 : 1;   // int64 vs int32

    const int s0 = (blockIdx.x * BSEG) / NCTA;
    const int s1 = ((blockIdx.x + 1) * BSEG) / NCTA;

    for (int b = s0; b < s1; b++) {
        int lo, hi;
        {
            int l = 0, h = NPTS;
            while (l < h) { int m = (l + h) >> 1; if (batch_words[m * stride] < b) l = m + 1; else h = m; }
            lo = l; h = NPTS;
            while (l < h) { int m = (l + h) >> 1; if (batch_words[m * stride] < b + 1) l = m + 1; else h = m; }
            hi = l;
        }

        // ---- pass 1: encoder + segmax -> seg_part ----
        if (tid < 128) pooled[tid] = 0;
        if (tid < 96)  actf[tid] = w_ne[tid];
        if (tid < 32)  actf[96 + tid] = b_ne[tid];
        __syncthreads();
        {
            float em[32];
#pragma unroll
            for (int j = 0; j < 32; j++) em[j] = 0.f;
            const float* wne = actf; const float* bne = actf + 96;
            for (int n = lo + tid; n < hi; n += NTHR) {
                float x = points[3 * n], y = points[3 * n + 1], z = points[3 * n + 2];
#pragma unroll
                for (int j = 0; j < 32; j++)
                    em[j] = fmaxf(em[j], bne[j] + x * wne[j] + y * wne[32 + j] + z * wne[64 + j]);
            }
#pragma unroll
            for (int j = 0; j < 32; j++) {
#pragma unroll
                for (int o = 16; o > 0; o >>= 1)
                    em[j] = fmaxf(em[j], __shfl_xor_sync(0xFFFFFFFFu, em[j], o));
            }
            if (lane == 0) {
#pragma unroll
                for (int j = 0; j < 32; j++) actf[128 + wid * 32 + j] = em[j];
            }
            __syncthreads();
            if (tid < 32) {
                float m = actf[128 + tid];
#pragma unroll
                for (int p = 1; p < 16; p++) m = fmaxf(m, actf[128 + p * 32 + tid]);
                actf[768 + tid] = m;
            }
            __syncthreads();
            if (tid < 128) {
                float s = b1[tid];
#pragma unroll
                for (int k = 0; k < 32; k++) s += actf[768 + k] * w1[k * 128 + tid];
                segp[tid] = s;
            }
            __syncthreads();
        }

        // ---- pass 2: 8 independent pair-slices of 16 pts, 128 pts per sweep ----
        // running max in regs across the whole segment; reduce once at the end
        float rm0[8], rm1[8];
#pragma unroll
        for (int j = 0; j < 8; j++) { rm0[j] = 0.f; rm1[j] = 0.f; }

        uint32_t offF = O_ACTF, offX = O_ACTX;

        int n0 = lo + rowbase;
        if (n0 < hi) {
            float4 f[4];
            {
                int n = n0 + (t64 >> 2), k0 = (t64 & 3) * 16;
#pragma unroll
                for (int i = 0; i < 4; i++)
                    f[i] = (n < hi) ? *(const float4*)(features + (size_t)n * 64 + k0 + 4 * i)
                                    : make_float4(0.f, 0.f, 0.f, 0.f);
            }
            stage_feats(sm, offF, rowbase, t64, f);
            PBAR(pair);

            for (; n0 < hi; n0 += 128) {
                // prefetch next sweep's features (overlaps L1/L2 compute)
                float4 fn[4];
                {
                    int nn = n0 + 128 + (t64 >> 2), k0 = (t64 & 3) * 16;
#pragma unroll
                    for (int i = 0; i < 4; i++)
                        fn[i] = (nn < hi) ? *(const float4*)(features + (size_t)nn * 64 + k0 + 4 * i)
                                          : make_float4(0.f, 0.f, 0.f, 0.f);
                }

                float acc[8][4];
                // layer 1: K=64, F -> X, bias = seg_part
#pragma unroll
                for (int nt = 0; nt < 8; nt++)
                    acc[nt][0] = acc[nt][1] = acc[nt][2] = acc[nt][3] = 0.f;
                run_layer<4>(smb + offF, smb + O_W1, rowbase, nh, lane, acc);
                epi_store(sm, offX, segp, acc, rowbase, nh, lane);
                PBAR(pair);

                // layer 2: K=128, X -> F, bias = b2
#pragma unroll
                for (int nt = 0; nt < 8; nt++)
                    acc[nt][0] = acc[nt][1] = acc[nt][2] = acc[nt][3] = 0.f;
                run_layer<8>(smb + offX, smb + O_W2, rowbase, nh, lane, acc);
                epi_store(sm, offF, b2s, acc, rowbase, nh, lane);
                PBAR(pair);

                // stage NEXT sweep's features into X (free after L2), overlapped with L3
                stage_feats(sm, offX, rowbase, t64, fn);

                // layer 3: K=128, reads F, bias = b3 -> masked running max in regs
#pragma unroll
                for (int nt = 0; nt < 8; nt++)
                    acc[nt][0] = acc[nt][1] = acc[nt][2] = acc[nt][3] = 0.f;
                run_layer<8>(smb + offF, smb + O_W3, rowbase, nh, lane, acc);
                {
                    const int r0 = lane >> 2;
                    const int c0 = 2 * (lane & 3);
                    bool v0 = (n0 + r0) < hi;
                    bool v1 = (n0 + r0 + 8) < hi;
#pragma unroll
                    for (int nt = 0; nt < 8; nt++) {
                        int col = nh * 64 + nt * 8 + c0;
                        float2 bb = *(const float2*)(b3s + col);
                        if (v0) {
                            rm0[nt] = fmaxf(rm0[nt], acc[nt][0] + bb.x);
                            rm1[nt] = fmaxf(rm1[nt], acc[nt][1] + bb.y);
                        }
                        if (v1) {
                            rm0[nt] = fmaxf(rm0[nt], acc[nt][2] + bb.x);
                            rm1[nt] = fmaxf(rm1[nt], acc[nt][3] + bb.y);
                        }
                    }
                }
                PBAR(pair);   // next features staged + F reads done
                uint32_t t = offF; offF = offX; offX = t;
            }
        }

        // ---- once per segment: reduce rm over the pair's 16 rows, then atomics ----
#pragma unroll
        for (int j = 0; j < 8; j++) {
#pragma unroll
            for (int o = 4; o < 32; o <<= 1) {
                rm0[j] = fmaxf(rm0[j], __shfl_xor_sync(0xFFFFFFFFu, rm0[j], o));
                rm1[j] = fmaxf(rm1[j], __shfl_xor_sync(0xFFFFFFFFu, rm1[j], o));
            }
        }
        if (lane < 4) {
#pragma unroll
            for (int nt = 0; nt < 8; nt++) {
                int col = nh * 64 + nt * 8 + 2 * lane;
                atomicMax(&pooled[col],     __float_as_int(rm0[nt]));
                atomicMax(&pooled[col + 1], __float_as_int(rm1[nt]));
            }
        }
        __syncthreads();

        // ---- pass 3: head MLP 128 -> 128 -> 64 -> 32 ----
        if (tid < 128) {
            float s = bg1[tid];
#pragma unroll 8
            for (int k = 0; k < 128; k++) s += __int_as_float(pooled[k]) * wg1[k * 128 + tid];
            actf[tid] = fmaxf(s, 0.f);
        }
        __syncthreads();
        if (tid < 64) {
            float s = bg2[tid];
#pragma unroll 8
            for (int k = 0; k < 128; k++) s += actf[k] * wg2[k * 64 + tid];
            actf[128 + tid] = fmaxf(s, 0.f);
        }
        __syncthreads();
        if (tid < 32) {
            float s = bg3[tid];
#pragma unroll 8
            for (int k = 0; k < 64; k++) s += actf[128 + k] * wg3[k * 32 + tid];
            out[b * 32 + tid] = fmaxf(s, 0.f);
        }
        __syncthreads();
    }
}

extern "C" void kernel_launch(void* const* d_in, const int* in_sizes, int n_in,
                              void* d_out, int out_size)
{
    const float* points   = (const float*)d_in[0];
    const float* features = (const float*)d_in[1];
    const int*   batchw   = (const int*)  d_in[2];
    const float* w_ne = (const float*)d_in[3];
    const float* b_ne = (const float*)d_in[4];
    const float* w1   = (const float*)d_in[5];
    const float* b1   = (const float*)d_in[6];
    const float* w2   = (const float*)d_in[7];
    const float* b2   = (const float*)d_in[8];
    const float* w3   = (const float*)d_in[9];
    const float* b3   = (const float*)d_in[10];
    const float* wg1  = (const float*)d_in[11];
    const float* bg1  = (const float*)d_in[12];
    const float* wg2  = (const float*)d_in[13];
    const float* bg2  = (const float*)d_in[14];
    const float* wg3  = (const float*)d_in[15];
    const float* bg3  = (const float*)d_in[16];
    float* out = (float*)d_out;

    cudaFuncSetAttribute(enc_kernel, cudaFuncAttributeMaxDynamicSharedMemorySize, SMEM_BYTES);
    enc_kernel<<<NCTA, NTHR, SMEM_BYTES>>>(
        points, features, batchw,
        w_ne, b_ne, w1, b1, w2, b2, w3, b3,
        wg1, bg1, wg2, bg2, wg3, bg3, out);
}

// round 12
// speedup vs baseline: 1.6308x; 1.0445x over previous
#include <cuda_runtime.h>
#include <cuda_fp16.h>
#include <cstdint>

#define NPTS 1048576
#define BSEG 2048
#define NCTA 148
#define NTHR 256

// smem byte offsets (all fp16; weights + acts)
//  W1: [128 o][64 k] SW128 (16KB)
//  W2, W3: 2 k-blocks of [128 o][64 k] (32KB each)
//  ACTF/ACTX: 2 act buffers, each 2 k-blocks of [128 rows][64 cols] fp16 (32KB each)
#define O_W1   0
#define O_W2   16384
#define O_W3   49152
#define O_ACTF 81920
#define O_ACTX 114688
#define O_SEGP 147456
#define O_POOL 147968
#define O_B2   148480
#define O_B3   148992
#define SMEM_BYTES 149504

#define SWZ(x) ((uint32_t)(x) ^ ((((uint32_t)(x)) >> 3) & 0x70))

__device__ __forceinline__ uint32_t smem_u32(const void* p) {
    uint32_t a;
    asm("{ .reg .u64 t; cvta.to.shared.u64 t, %1; cvt.u32.u64 %0, t; }" : "=r"(a) : "l"(p));
    return a;
}
__device__ __forceinline__ void ldsm_x4(uint32_t addr, uint32_t r[4]) {
    asm volatile("ldmatrix.sync.aligned.m8n8.x4.shared.b16 {%0,%1,%2,%3}, [%4];"
        : "=r"(r[0]), "=r"(r[1]), "=r"(r[2]), "=r"(r[3]) : "r"(addr));
}
__device__ __forceinline__ void mma16816(float c[4], const uint32_t a[4], const uint32_t b0, const uint32_t b1) {
    asm volatile("mma.sync.aligned.m16n8k16.row.col.f32.f16.f16.f32 "
        "{%0,%1,%2,%3},{%4,%5,%6,%7},{%8,%9},{%0,%1,%2,%3};"
        : "+f"(c[0]), "+f"(c[1]), "+f"(c[2]), "+f"(c[3])
        : "r"(a[0]), "r"(a[1]), "r"(a[2]), "r"(a[3]), "r"(b0), "r"(b1));
}

// pack two floats -> one fp16x2 word (single F2FP instruction)
__device__ __forceinline__ uint32_t packh2(float v0, float v1) {
    __half2 h = __floats2half2_rn(v0, v1);
    return *(uint32_t*)&h;
}

// one layer, FULL 128 output cols per warp: acc[16 nt][4] += A[16 x K] * W[K x 128]
// W fragments consumed immediately (4 transient regs) to bound register pressure.
template<int KSTEPS>
__device__ __forceinline__ void run_layer(uint32_t aBase, uint32_t wBase,
                                          int rowbase, int lane, float acc[16][4])
{
    const int arow  = rowbase + (lane & 15);
    const int acol  = (lane >> 4) * 8;
    const int wrow  = ((lane >> 4) << 3) + (lane & 7);
    const int wcsel = ((lane >> 3) & 1) << 3;
#pragma unroll
    for (int s = 0; s < KSTEPS; s++) {
        const int kb = s >> 2, kk = (s & 3) * 16;
        uint32_t ah[4];
        ldsm_x4(aBase + (uint32_t)kb * 16384 + SWZ(arow * 128 + (kk + acol) * 2), ah);
#pragma unroll
        for (int p8 = 0; p8 < 8; p8++) {
            uint32_t wh[4];
            ldsm_x4(wBase + (uint32_t)kb * 16384 + SWZ((p8 * 16 + wrow) * 128 + (kk + wcsel) * 2), wh);
            mma16816(acc[p8 * 2],     ah, wh[0], wh[1]);
            mma16816(acc[p8 * 2 + 1], ah, wh[2], wh[3]);
        }
    }
}

// epilogue: bias + relu -> fp16 -> swizzled act buffer (warp-private 16 rows x 128 cols)
__device__ __forceinline__ void epi_store(char* sm_, uint32_t outOff,
                                          const float* bias, float acc[16][4],
                                          int rowbase, int lane)
{
    const int row = rowbase + (lane >> 2);
    const int c0  = 2 * (lane & 3);
#pragma unroll
    for (int nt = 0; nt < 16; nt++) {
        int col = nt * 8 + c0;
        float2 bb = *(const float2*)(bias + col);
        uint32_t kbb = (uint32_t)(col >> 6) * 16384;
        int kk = col & 63;
        *(uint32_t*)(sm_ + outOff + kbb + SWZ(row * 128 + kk * 2)) =
            packh2(fmaxf(acc[nt][0] + bb.x, 0.f), fmaxf(acc[nt][1] + bb.y, 0.f));
        *(uint32_t*)(sm_ + outOff + kbb + SWZ((row + 8) * 128 + kk * 2)) =
            packh2(fmaxf(acc[nt][2] + bb.x, 0.f), fmaxf(acc[nt][3] + bb.y, 0.f));
    }
}

// stage the warp's 16 feature rows (64 fp32 cols) into buffer k-block 0.
// lane>>1 = row (0..15), (lane&1)*32 = col half; 8 float4 LDG in flight per lane.
__device__ __forceinline__ void stage_feats(char* sm_, uint32_t bufOff, int rowbase, int lane,
                                            const float* __restrict__ feats, int n0, int hi)
{
    int r  = lane >> 1;
    int n  = n0 + r;
    int k0 = (lane & 1) * 32;
    float4 f[8];
    if (n < hi) {
        const float4* src = (const float4*)(feats + (size_t)n * 64 + k0);
#pragma unroll
        for (int i = 0; i < 8; i++) f[i] = src[i];
    } else {
#pragma unroll
        for (int i = 0; i < 8; i++) f[i] = make_float4(0.f, 0.f, 0.f, 0.f);
    }
    int row = rowbase + r;
#pragma unroll
    for (int i = 0; i < 8; i++) {
        int k = k0 + 4 * i;
        *(uint32_t*)(sm_ + bufOff + SWZ(row * 128 + k * 2))       = packh2(f[i].x, f[i].y);
        *(uint32_t*)(sm_ + bufOff + SWZ(row * 128 + (k + 2) * 2)) = packh2(f[i].z, f[i].w);
    }
}

__global__ void __launch_bounds__(NTHR, 1)
enc_kernel(const float* __restrict__ points, const float* __restrict__ features,
           const int* __restrict__ batch_words,
           const float* __restrict__ w_ne, const float* __restrict__ b_ne,
           const float* __restrict__ w1, const float* __restrict__ b1,
           const float* __restrict__ w2, const float* __restrict__ b2,
           const float* __restrict__ w3, const float* __restrict__ b3,
           const float* __restrict__ wg1, const float* __restrict__ bg1,
           const float* __restrict__ wg2, const float* __restrict__ bg2,
           const float* __restrict__ wg3, const float* __restrict__ bg3,
           float* __restrict__ out)
{
    extern __shared__ char sm[];
    const int tid = threadIdx.x, lane = tid & 31, wid = tid >> 5;
    const int rowbase = wid * 16;             // warp-private 16 rows
    const uint32_t smb = smem_u32(sm);

    float* segp   = (float*)(sm + O_SEGP);
    int*   pooled = (int*)(sm + O_POOL);
    float* b2s    = (float*)(sm + O_B2);
    float* b3s    = (float*)(sm + O_B3);
    float* actf   = (float*)(sm + O_ACTF);    // pass-1 / head scratch alias

    // ---- stage weights fp16, transposed [o][k], SW128 k-blocks ----
    for (int idx = tid; idx < 8192; idx += NTHR) {         // W1 rows 32..95
        int k = idx >> 7, o = idx & 127;
        *(unsigned short*)(sm + O_W1 + SWZ(o * 128 + k * 2)) =
            __half_as_ushort(__float2half_rn(w1[(32 + k) * 128 + o]));
    }
    for (int idx = tid; idx < 16384; idx += NTHR) {
        int k = idx >> 7, o = idx & 127;
        uint32_t off = (uint32_t)(k >> 6) * 16384 + SWZ(o * 128 + (k & 63) * 2);
        *(unsigned short*)(sm + O_W2 + off) = __half_as_ushort(__float2half_rn(w2[k * 128 + o]));
        *(unsigned short*)(sm + O_W3 + off) = __half_as_ushort(__float2half_rn(w3[k * 128 + o]));
    }
    if (tid < 128) { b2s[tid] = b2[tid]; b3s[tid] = b3[tid]; }
    __syncthreads();

    const int stride = (batch_words[NPTS - 1] == 0) ? 2 : 1;   // int64 vs int32

    const int s0 = (blockIdx.x * BSEG) / NCTA;
    const int s1 = ((blockIdx.x + 1) * BSEG) / NCTA;

    for (int b = s0; b < s1; b++) {
        int lo, hi;
        {
            int l = 0, h = NPTS;
            while (l < h) { int m = (l + h) >> 1; if (batch_words[m * stride] < b) l = m + 1; else h = m; }
            lo = l; h = NPTS;
            while (l < h) { int m = (l + h) >> 1; if (batch_words[m * stride] < b + 1) l = m + 1; else h = m; }
            hi = l;
        }

        // ---- pass 1: encoder + segmax -> seg_part ----
        if (tid < 128) pooled[tid] = 0;
        if (tid < 96)  actf[tid] = w_ne[tid];
        if (tid < 32)  actf[96 + tid] = b_ne[tid];
        __syncthreads();
        {
            float em[32];
#pragma unroll
            for (int j = 0; j < 32; j++) em[j] = 0.f;
            const float* wne = actf; const float* bne = actf + 96;
            for (int n = lo + tid; n < hi; n += NTHR) {
                float x = points[3 * n], y = points[3 * n + 1], z = points[3 * n + 2];
#pragma unroll
                for (int j = 0; j < 32; j++)
                    em[j] = fmaxf(em[j], bne[j] + x * wne[j] + y * wne[32 + j] + z * wne[64 + j]);
            }
#pragma unroll
            for (int j = 0; j < 32; j++) {
#pragma unroll
                for (int o = 16; o > 0; o >>= 1)
                    em[j] = fmaxf(em[j], __shfl_xor_sync(0xFFFFFFFFu, em[j], o));
            }
            if (lane == 0) {
#pragma unroll
                for (int j = 0; j < 32; j++) actf[128 + wid * 32 + j] = em[j];
            }
            __syncthreads();
            if (tid < 32) {
                float m = actf[128 + tid];
#pragma unroll
                for (int p = 1; p < 8; p++) m = fmaxf(m, actf[128 + p * 32 + tid]);
                actf[512 + tid] = m;
            }
            __syncthreads();
            if (tid < 128) {
                float s = b1[tid];
#pragma unroll
                for (int k = 0; k < 32; k++) s += actf[512 + k] * w1[k * 128 + tid];
                segp[tid] = s;
            }
            __syncthreads();
        }

        // ---- pass 2: warp-private 16-row slices; NO barriers in the mainloop ----
        float rm0[16], rm1[16];
#pragma unroll
        for (int j = 0; j < 16; j++) { rm0[j] = 0.f; rm1[j] = 0.f; }

        uint32_t offF = O_ACTF, offX = O_ACTX;

        int n0 = lo + rowbase;
        if (n0 < hi) {
            stage_feats(sm, offF, rowbase, lane, features, n0, hi);
            __syncwarp();

            for (; n0 < hi; n0 += 128) {
                float acc[16][4];
                // layer 1: K=64, F(kb0) -> X, bias = seg_part
#pragma unroll
                for (int nt = 0; nt < 16; nt++)
                    acc[nt][0] = acc[nt][1] = acc[nt][2] = acc[nt][3] = 0.f;
                run_layer<4>(smb + offF, smb + O_W1, rowbase, lane, acc);
                epi_store(sm, offX, segp, acc, rowbase, lane);
                __syncwarp();

                // layer 2: K=128, X -> F, bias = b2
#pragma unroll
                for (int nt = 0; nt < 16; nt++)
                    acc[nt][0] = acc[nt][1] = acc[nt][2] = acc[nt][3] = 0.f;
                run_layer<8>(smb + offX, smb + O_W2, rowbase, lane, acc);
                epi_store(sm, offF, b2s, acc, rowbase, lane);
                __syncwarp();

                // stage NEXT sweep's features into X kb0 (X free after L2); overlaps L3
                stage_feats(sm, offX, rowbase, lane, features, n0 + 128, hi);

                // layer 3: K=128, reads F, bias = b3 -> masked running max in regs
#pragma unroll
                for (int nt = 0; nt < 16; nt++)
                    acc[nt][0] = acc[nt][1] = acc[nt][2] = acc[nt][3] = 0.f;
                run_layer<8>(smb + offF, smb + O_W3, rowbase, lane, acc);
                {
                    const int r0 = lane >> 2;
                    const int c0 = 2 * (lane & 3);
                    bool v0 = (n0 + r0) < hi;
                    bool v1 = (n0 + r0 + 8) < hi;
#pragma unroll
                    for (int nt = 0; nt < 16; nt++) {
                        int col = nt * 8 + c0;
                        float2 bb = *(const float2*)(b3s + col);
                        if (v0) {
                            rm0[nt] = fmaxf(rm0[nt], acc[nt][0] + bb.x);
                            rm1[nt] = fmaxf(rm1[nt], acc[nt][1] + bb.y);
                        }
                        if (v1) {
                            rm0[nt] = fmaxf(rm0[nt], acc[nt][2] + bb.x);
                            rm1[nt] = fmaxf(rm1[nt], acc[nt][3] + bb.y);
                        }
                    }
                }
                __syncwarp();
                uint32_t t = offF; offF = offX; offX = t;
            }
        }

        // ---- once per segment: reduce rm over the warp's 16 rows, then atomics ----
#pragma unroll
        for (int j = 0; j < 16; j++) {
#pragma unroll
            for (int o = 4; o < 32; o <<= 1) {
                rm0[j] = fmaxf(rm0[j], __shfl_xor_sync(0xFFFFFFFFu, rm0[j], o));
                rm1[j] = fmaxf(rm1[j], __shfl_xor_sync(0xFFFFFFFFu, rm1[j], o));
            }
        }
        if (lane < 4) {
#pragma unroll
            for (int nt = 0; nt < 16; nt++) {
                int col = nt * 8 + 2 * lane;
                atomicMax(&pooled[col],     __float_as_int(rm0[nt]));
                atomicMax(&pooled[col + 1], __float_as_int(rm1[nt]));
            }
        }
        __syncthreads();

        // ---- pass 3: head MLP 128 -> 128 -> 64 -> 32 ----
        if (tid < 128) {
            float s = bg1[tid];
#pragma unroll 8
            for (int k = 0; k < 128; k++) s += __int_as_float(pooled[k]) * wg1[k * 128 + tid];
            actf[tid] = fmaxf(s, 0.f);
        }
        __syncthreads();
        if (tid < 64) {
            float s = bg2[tid];
#pragma unroll 8
            for (int k = 0; k < 128; k++) s += actf[k] * wg2[k * 64 + tid];
            actf[128 + tid] = fmaxf(s, 0.f);
        }
        __syncthreads();
        if (tid < 32) {
            float s = bg3[tid];
#pragma unroll 8
            for (int k = 0; k < 64; k++) s += actf[128 + k] * wg3[k * 32 + tid];
            out[b * 32 + tid] = fmaxf(s, 0.f);
        }
        __syncthreads();
    }
}

extern "C" void kernel_launch(void* const* d_in, const int* in_sizes, int n_in,
                              void* d_out, int out_size)
{
    const float* points   = (const float*)d_in[0];
    const float* features = (const float*)d_in[1];
    const int*   batchw   = (const int*)  d_in[2];
    const float* w_ne = (const float*)d_in[3];
    const float* b_ne = (const float*)d_in[4];
    const float* w1   = (const float*)d_in[5];
    const float* b1   = (const float*)d_in[6];
    const float* w2   = (const float*)d_in[7];
    const float* b2   = (const float*)d_in[8];
    const float* w3   = (const float*)d_in[9];
    const float* b3   = (const float*)d_in[10];
    const float* wg1  = (const float*)d_in[11];
    const float* bg1  = (const float*)d_in[12];
    const float* wg2  = (const float*)d_in[13];
    const float* bg2  = (const float*)d_in[14];
    const float* wg3  = (const float*)d_in[15];
    const float* bg3  = (const float*)d_in[16];
    float* out = (float*)d_out;

    cudaFuncSetAttribute(enc_kernel, cudaFuncAttributeMaxDynamicSharedMemorySize, SMEM_BYTES);
    enc_kernel<<<NCTA, NTHR, SMEM_BYTES>>>(
        points, features, batchw,
        w_ne, b_ne, w1, b1, w2, b2, w3, b3,
        wg1, bg1, wg2, bg2, wg3, bg3, out);
}